// round 5
// baseline (speedup 1.0000x reference)
#include <cuda_runtime.h>
#include <cuda_bf16.h>
#include <cstdint>
#include <cstddef>

// Problem constants
#define BB   512
#define KK   512
#define DIN  1024
#define DOUT 4096
#define C3K  1536          // 3*K
#define NROWS (BB*KK)      // 262144
#define NKT  (C3K/16)      // 96 k-tiles

typedef unsigned long long ull;

// Scratch (static device globals — no allocation)
__device__ float g_y[BB * C3K];     // [b][o*512 + k], 3 MB
__device__ float g_stats[6];        // sum[3], sumsq[3]
__device__ float g_coef[6];         // scale[3], shift[3]

// ---------------------------------------------------------------------------
// Kernel A (round-3 version): y = x @ W_emb^T + b. One warp per row,
// W_emb register-resident. Zeroes g_stats for this replay.
// ---------------------------------------------------------------------------
__global__ __launch_bounds__(256) void k_embed(const float* __restrict__ x,
                                               const float* __restrict__ Wemb,
                                               const float* __restrict__ bemb) {
    const int tid = threadIdx.x;
    if (blockIdx.x == 0 && tid < 6) g_stats[tid] = 0.0f;
    const int lane = tid & 31;

    float4 w0[8], w1[8], w2[8];
    const float4* W4 = (const float4*)Wemb;
#pragma unroll
    for (int j = 0; j < 8; j++) {
        w0[j] = W4[      j * 32 + lane];
        w1[j] = W4[256 + j * 32 + lane];
        w2[j] = W4[512 + j * 32 + lane];
    }
    const float b0 = bemb[0], b1 = bemb[1], b2 = bemb[2];

    int gw = blockIdx.x * 8 + (tid >> 5);
    const int nw = gridDim.x * 8;
    for (int row = gw; row < NROWS; row += nw) {
        const float4* xr = (const float4*)x + (size_t)row * 256;
        float a0 = 0.f, a1 = 0.f, a2 = 0.f;
#pragma unroll
        for (int j = 0; j < 8; j++) {
            float4 xv = xr[j * 32 + lane];
            a0 += xv.x * w0[j].x + xv.y * w0[j].y + xv.z * w0[j].z + xv.w * w0[j].w;
            a1 += xv.x * w1[j].x + xv.y * w1[j].y + xv.z * w1[j].z + xv.w * w1[j].w;
            a2 += xv.x * w2[j].x + xv.y * w2[j].y + xv.z * w2[j].z + xv.w * w2[j].w;
        }
#pragma unroll
        for (int off = 16; off; off >>= 1) {
            a0 += __shfl_xor_sync(0xffffffffu, a0, off);
            a1 += __shfl_xor_sync(0xffffffffu, a1, off);
            a2 += __shfl_xor_sync(0xffffffffu, a2, off);
        }
        if (lane == 0) {
            const int b = row >> 9, k = row & 511;
            float* yb = g_y + (size_t)b * C3K + k;
            yb[0]    = a0 + b0;
            yb[512]  = a1 + b1;
            yb[1024] = a2 + b2;
        }
    }
}

// ---------------------------------------------------------------------------
// Kernel B1: per-channel sum / sumsq over g_y
// ---------------------------------------------------------------------------
__global__ __launch_bounds__(256) void k_stats() {
    float s[3] = {0.f, 0.f, 0.f};
    float q[3] = {0.f, 0.f, 0.f};
    const int stride = gridDim.x * blockDim.x;
    const float4* y4 = (const float4*)g_y;
    const int n4 = (BB * C3K) / 4;
    for (int i = blockIdx.x * blockDim.x + threadIdx.x; i < n4; i += stride) {
        const int o = (i % 384) >> 7;
        float4 v = y4[i];
        s[o] += v.x + v.y + v.z + v.w;
        q[o] += v.x * v.x + v.y * v.y + v.z * v.z + v.w * v.w;
    }
#pragma unroll
    for (int off = 16; off; off >>= 1) {
#pragma unroll
        for (int o = 0; o < 3; o++) {
            s[o] += __shfl_xor_sync(0xffffffffu, s[o], off);
            q[o] += __shfl_xor_sync(0xffffffffu, q[o], off);
        }
    }
    __shared__ float rs[6];
    if (threadIdx.x < 6) rs[threadIdx.x] = 0.f;
    __syncthreads();
    if ((threadIdx.x & 31) == 0) {
#pragma unroll
        for (int o = 0; o < 3; o++) {
            atomicAdd(&rs[o], s[o]);
            atomicAdd(&rs[3 + o], q[o]);
        }
    }
    __syncthreads();
    if (threadIdx.x < 6) atomicAdd(&g_stats[threadIdx.x], rs[threadIdx.x]);
}

// ---------------------------------------------------------------------------
// Kernel B2: finalize BN affine
// ---------------------------------------------------------------------------
__global__ void k_final(const float* __restrict__ gamma, const float* __restrict__ beta) {
    const int o = threadIdx.x;
    if (o < 3) {
        const float n = (float)NROWS;
        float mean = g_stats[o] / n;
        float var  = g_stats[3 + o] / n - mean * mean;
        float sc   = gamma[o] * rsqrtf(var + 1e-5f);
        g_coef[o]     = sc;
        g_coef[3 + o] = beta[o] - mean * sc;
    }
}

// ---------------------------------------------------------------------------
// Kernel C: out[512,4096] = (g_y*scale+shift) @ W_fc2^T via fma.rn.f32x2.
// CTA tile 128x128, K-tile 16, double-buffered SMEM.
// A stored normally (row pairs read as packed f32x2 operands directly);
// B stored DUPLICATED ({v,v} per element) so b operands are packed directly.
// No per-FMA mov duplication. Warp tile 32Mx64N, lane (am,an)=(l>>3,l&7).
// ---------------------------------------------------------------------------
#define BROW 268   // padded Bdup row length in floats (16B-aligned, conflict-spread)

__global__ __launch_bounds__(256) void k_gemm2(const float* __restrict__ W,
                                               float* __restrict__ out) {
    __shared__ float As[2][16][132];
    __shared__ float Bs[2][16][BROW];   // duplicated: Bs[kk][2n]=Bs[kk][2n+1]=B[n]

    const int tid = threadIdx.x;
    const int wid  = tid >> 5;
    const int lane = tid & 31;
    const int warp_m = wid & 3;        // 0..3
    const int warp_n = wid >> 2;       // 0..1
    const int am = lane >> 3;          // 0..3
    const int an = lane & 7;           // 0..7
    const int arow = warp_m * 32 + am * 8;   // A row base in tile (8 rows)
    const int bcol = warp_n * 64 + an * 4;   // B col base (group 0); group 1 at +32

    const int bn = blockIdx.x;    // 0..31
    const int bm = blockIdx.y;    // 0..3

    const int lr = tid >> 2;           // loader row 0..63
    const int lc = (tid & 3) * 4;      // loader col (of 16)

    const float* Ap = g_y + ((size_t)(bm * 128 + lr)) * C3K + lc;
    const float* Bp = W   + ((size_t)(bn * 128 + lr)) * C3K + lc;

    // accp[j][i2]: cols (bcol + [j<4? j : 32+j-4]), rows {arow+2*i2, arow+2*i2+1}
    ull accp[8][4];
#pragma unroll
    for (int j = 0; j < 8; j++)
#pragma unroll
        for (int i2 = 0; i2 < 4; i2++) accp[j][i2] = 0ull;

    // Prologue: k-tile 0 -> stage 0
    {
        const float sc = g_coef[0], sh = g_coef[3];
        float4 a0  = *(const float4*)(Ap);
        float4 a1  = *(const float4*)(Ap + (size_t)64 * C3K);
        float4 bb0 = *(const float4*)(Bp);
        float4 bb1 = *(const float4*)(Bp + (size_t)64 * C3K);
#pragma unroll
        for (int i = 0; i < 4; i++) {
            float av0 = (&a0.x)[i] * sc + sh;
            float av1 = (&a1.x)[i] * sc + sh;
            As[0][lc + i][lr]      = av0;
            As[0][lc + i][lr + 64] = av1;
            float bv0 = (&bb0.x)[i];
            float bv1 = (&bb1.x)[i];
            *(float2*)&Bs[0][lc + i][2 * lr]        = make_float2(bv0, bv0);
            *(float2*)&Bs[0][lc + i][2 * (lr + 64)] = make_float2(bv1, bv1);
        }
    }
    __syncthreads();

    for (int kt = 0; kt < NKT; kt++) {
        const int s = kt & 1;

        // Prefetch next k-tile from global (overlaps compute)
        float4 a0, a1, bb0, bb1;
        float sc = 0.f, sh = 0.f;
        const bool more = (kt + 1 < NKT);
        if (more) {
            const int o = (kt + 1) >> 5;
            sc = g_coef[o];
            sh = g_coef[3 + o];
            a0  = *(const float4*)(Ap + (size_t)(kt + 1) * 16);
            a1  = *(const float4*)(Ap + (size_t)(kt + 1) * 16 + (size_t)64 * C3K);
            bb0 = *(const float4*)(Bp + (size_t)(kt + 1) * 16);
            bb1 = *(const float4*)(Bp + (size_t)(kt + 1) * 16 + (size_t)64 * C3K);
        }

        // Compute on stage s
#pragma unroll
        for (int kk = 0; kk < 16; kk++) {
            // A row pairs: 8 rows -> 4 packed f32x2 operands (direct LDS.128)
            ulonglong2 av0 = *(const ulonglong2*)&As[s][kk][arow];
            ulonglong2 av1 = *(const ulonglong2*)&As[s][kk][arow + 4];
            ull apair[4] = {av0.x, av0.y, av1.x, av1.y};
            // B duplicated pairs: group0 cols bcol..+3, group1 cols bcol+32..+35
            ulonglong2 bv0 = *(const ulonglong2*)&Bs[s][kk][2 * bcol];
            ulonglong2 bv1 = *(const ulonglong2*)&Bs[s][kk][2 * bcol + 4];
            ulonglong2 bv2 = *(const ulonglong2*)&Bs[s][kk][2 * bcol + 64];
            ulonglong2 bv3 = *(const ulonglong2*)&Bs[s][kk][2 * bcol + 68];
            ull bdup[8] = {bv0.x, bv0.y, bv1.x, bv1.y, bv2.x, bv2.y, bv3.x, bv3.y};
#pragma unroll
            for (int j = 0; j < 8; j++) {
#pragma unroll
                for (int i2 = 0; i2 < 4; i2++) {
                    asm("fma.rn.f32x2 %0, %1, %2, %0;"
                        : "+l"(accp[j][i2]) : "l"(bdup[j]), "l"(apair[i2]));
                }
            }
        }

        // Store prefetched tile into the other stage
        if (more) {
            const int d = s ^ 1;
#pragma unroll
            for (int i = 0; i < 4; i++) {
                float av0 = (&a0.x)[i] * sc + sh;
                float av1 = (&a1.x)[i] * sc + sh;
                As[d][lc + i][lr]      = av0;
                As[d][lc + i][lr + 64] = av1;
                float bv0 = (&bb0.x)[i];
                float bv1 = (&bb1.x)[i];
                *(float2*)&Bs[d][lc + i][2 * lr]        = make_float2(bv0, bv0);
                *(float2*)&Bs[d][lc + i][2 * (lr + 64)] = make_float2(bv1, bv1);
            }
        }
        __syncthreads();
    }

    // Epilogue: row m = arow + i; acc[j][i>>1] lo/hi by (i&1)
    float* Cp = out + ((size_t)(bm * 128 + arow)) * DOUT + bn * 128 + bcol;
#pragma unroll
    for (int i = 0; i < 8; i++) {
        const int i2 = i >> 1, h = i & 1;
        float v[8];
#pragma unroll
        for (int j = 0; j < 8; j++) {
            union { ull u; float2 f; } c;
            c.u = accp[j][i2];
            v[j] = h ? c.f.y : c.f.x;
        }
        *(float4*)(Cp + (size_t)i * DOUT)      = make_float4(v[0], v[1], v[2], v[3]);
        *(float4*)(Cp + (size_t)i * DOUT + 32) = make_float4(v[4], v[5], v[6], v[7]);
    }
}

// ---------------------------------------------------------------------------
// Launch
// ---------------------------------------------------------------------------
extern "C" void kernel_launch(void* const* d_in, const int* in_sizes, int n_in,
                              void* d_out, int out_size) {
    const float* x     = (const float*)d_in[0];
    const float* Wemb  = (const float*)d_in[1];
    const float* bemb  = (const float*)d_in[2];
    const float* gamma = (const float*)d_in[3];
    const float* beta  = (const float*)d_in[4];
    const float* Wfc2  = (const float*)d_in[5];
    float* out = (float*)d_out;

    k_embed<<<1184, 256>>>(x, Wemb, bemb);
    k_stats<<<96, 256>>>();
    k_final<<<1, 32>>>(gamma, beta);
    k_gemm2<<<dim3(32, 4), 256>>>(Wfc2, out);
}

// round 6
// speedup vs baseline: 1.6381x; 1.6381x over previous
#include <cuda_runtime.h>
#include <cuda_bf16.h>
#include <cstdint>
#include <cstddef>

// Problem constants
#define BB   512
#define KK   512
#define DIN  1024
#define DOUT 4096
#define C3K  1536          // 3*K
#define NROWS (BB*KK)      // 262144
#define NKT16 (C3K/16)     // 96 k16-tiles

typedef unsigned long long ull;

// Scratch (static device globals — no allocation)
__device__ float g_y[BB * C3K];     // [b][o*512 + k], 3 MB
__device__ float g_stats[6];
__device__ float g_coef[6];
__device__ __align__(16) __nv_bfloat16 g_Ah[BB * C3K];
__device__ __align__(16) __nv_bfloat16 g_Al[BB * C3K];
__device__ __align__(16) __nv_bfloat16 g_Bh[DOUT * C3K];
__device__ __align__(16) __nv_bfloat16 g_Bl[DOUT * C3K];

// ---------------------------------------------------------------------------
// Kernel A: y = x @ W_emb^T + b. One warp per row, W_emb register-resident.
// ---------------------------------------------------------------------------
__global__ __launch_bounds__(256) void k_embed(const float* __restrict__ x,
                                               const float* __restrict__ Wemb,
                                               const float* __restrict__ bemb) {
    const int tid = threadIdx.x;
    if (blockIdx.x == 0 && tid < 6) g_stats[tid] = 0.0f;
    const int lane = tid & 31;

    float4 w0[8], w1[8], w2[8];
    const float4* W4 = (const float4*)Wemb;
#pragma unroll
    for (int j = 0; j < 8; j++) {
        w0[j] = W4[      j * 32 + lane];
        w1[j] = W4[256 + j * 32 + lane];
        w2[j] = W4[512 + j * 32 + lane];
    }
    const float b0 = bemb[0], b1 = bemb[1], b2 = bemb[2];

    int gw = blockIdx.x * 8 + (tid >> 5);
    const int nw = gridDim.x * 8;
    for (int row = gw; row < NROWS; row += nw) {
        const float4* xr = (const float4*)x + (size_t)row * 256;
        float a0 = 0.f, a1 = 0.f, a2 = 0.f;
#pragma unroll
        for (int j = 0; j < 8; j++) {
            float4 xv = xr[j * 32 + lane];
            a0 += xv.x * w0[j].x + xv.y * w0[j].y + xv.z * w0[j].z + xv.w * w0[j].w;
            a1 += xv.x * w1[j].x + xv.y * w1[j].y + xv.z * w1[j].z + xv.w * w1[j].w;
            a2 += xv.x * w2[j].x + xv.y * w2[j].y + xv.z * w2[j].z + xv.w * w2[j].w;
        }
#pragma unroll
        for (int off = 16; off; off >>= 1) {
            a0 += __shfl_xor_sync(0xffffffffu, a0, off);
            a1 += __shfl_xor_sync(0xffffffffu, a1, off);
            a2 += __shfl_xor_sync(0xffffffffu, a2, off);
        }
        if (lane == 0) {
            const int b = row >> 9, k = row & 511;
            float* yb = g_y + (size_t)b * C3K + k;
            yb[0]    = a0 + b0;
            yb[512]  = a1 + b1;
            yb[1024] = a2 + b2;
        }
    }
}

// ---------------------------------------------------------------------------
// Kernel B1: per-channel sum / sumsq over g_y
// ---------------------------------------------------------------------------
__global__ __launch_bounds__(256) void k_stats() {
    float s[3] = {0.f, 0.f, 0.f};
    float q[3] = {0.f, 0.f, 0.f};
    const int stride = gridDim.x * blockDim.x;
    const float4* y4 = (const float4*)g_y;
    const int n4 = (BB * C3K) / 4;
    for (int i = blockIdx.x * blockDim.x + threadIdx.x; i < n4; i += stride) {
        const int o = (i % 384) >> 7;
        float4 v = y4[i];
        s[o] += v.x + v.y + v.z + v.w;
        q[o] += v.x * v.x + v.y * v.y + v.z * v.z + v.w * v.w;
    }
#pragma unroll
    for (int off = 16; off; off >>= 1) {
#pragma unroll
        for (int o = 0; o < 3; o++) {
            s[o] += __shfl_xor_sync(0xffffffffu, s[o], off);
            q[o] += __shfl_xor_sync(0xffffffffu, q[o], off);
        }
    }
    __shared__ float rs[6];
    if (threadIdx.x < 6) rs[threadIdx.x] = 0.f;
    __syncthreads();
    if ((threadIdx.x & 31) == 0) {
#pragma unroll
        for (int o = 0; o < 3; o++) {
            atomicAdd(&rs[o], s[o]);
            atomicAdd(&rs[3 + o], q[o]);
        }
    }
    __syncthreads();
    if (threadIdx.x < 6) atomicAdd(&g_stats[threadIdx.x], rs[threadIdx.x]);
}

// ---------------------------------------------------------------------------
// Kernel B2: finalize BN affine
// ---------------------------------------------------------------------------
__global__ void k_final(const float* __restrict__ gamma, const float* __restrict__ beta) {
    const int o = threadIdx.x;
    if (o < 3) {
        const float n = (float)NROWS;
        float mean = g_stats[o] / n;
        float var  = g_stats[3 + o] / n - mean * mean;
        float sc   = gamma[o] * rsqrtf(var + 1e-5f);
        g_coef[o]     = sc;
        g_coef[3 + o] = beta[o] - mean * sc;
    }
}

// ---------------------------------------------------------------------------
// convA: normalize g_y and split into bf16 hi/lo
// ---------------------------------------------------------------------------
__global__ __launch_bounds__(256) void k_convA() {
    const int n4 = (BB * C3K) / 4;
    const int stride = gridDim.x * blockDim.x;
    const float4* y4 = (const float4*)g_y;
    for (int i = blockIdx.x * blockDim.x + threadIdx.x; i < n4; i += stride) {
        const int o = (i % 384) >> 7;
        const float sc = g_coef[o], sh = g_coef[3 + o];
        float4 v = y4[i];
        float a[4] = {v.x * sc + sh, v.y * sc + sh, v.z * sc + sh, v.w * sc + sh};
        __nv_bfloat16 h[4], l[4];
#pragma unroll
        for (int j = 0; j < 4; j++) {
            h[j] = __float2bfloat16_rn(a[j]);
            l[j] = __float2bfloat16_rn(a[j] - __bfloat162float(h[j]));
        }
        ((__nv_bfloat162*)g_Ah)[i * 2 + 0] = __nv_bfloat162(h[0], h[1]);
        ((__nv_bfloat162*)g_Ah)[i * 2 + 1] = __nv_bfloat162(h[2], h[3]);
        ((__nv_bfloat162*)g_Al)[i * 2 + 0] = __nv_bfloat162(l[0], l[1]);
        ((__nv_bfloat162*)g_Al)[i * 2 + 1] = __nv_bfloat162(l[2], l[3]);
    }
}

// ---------------------------------------------------------------------------
// convB: split W_fc2 into bf16 hi/lo
// ---------------------------------------------------------------------------
__global__ __launch_bounds__(256) void k_convB(const float* __restrict__ W) {
    const int n4 = (DOUT * C3K) / 4;
    const int stride = gridDim.x * blockDim.x;
    const float4* w4 = (const float4*)W;
    for (int i = blockIdx.x * blockDim.x + threadIdx.x; i < n4; i += stride) {
        float4 v = w4[i];
        float a[4] = {v.x, v.y, v.z, v.w};
        __nv_bfloat16 h[4], l[4];
#pragma unroll
        for (int j = 0; j < 4; j++) {
            h[j] = __float2bfloat16_rn(a[j]);
            l[j] = __float2bfloat16_rn(a[j] - __bfloat162float(h[j]));
        }
        ((__nv_bfloat162*)g_Bh)[i * 2 + 0] = __nv_bfloat162(h[0], h[1]);
        ((__nv_bfloat162*)g_Bh)[i * 2 + 1] = __nv_bfloat162(h[2], h[3]);
        ((__nv_bfloat162*)g_Bl)[i * 2 + 0] = __nv_bfloat162(l[0], l[1]);
        ((__nv_bfloat162*)g_Bl)[i * 2 + 1] = __nv_bfloat162(l[2], l[3]);
    }
}

// ---------------------------------------------------------------------------
// k_mma: out = A @ B^T via mma.sync m16n8k16 bf16, 3-product split.
// CTA 128x128, 8 warps 32Mx64N, 96 k16 tiles, double-buffered swizzled SMEM.
// ---------------------------------------------------------------------------
#define LDSM_X4(r0, r1, r2, r3, a) \
    asm volatile("ldmatrix.sync.aligned.m8n8.x4.shared.b16 {%0,%1,%2,%3}, [%4];" \
                 : "=r"(r0), "=r"(r1), "=r"(r2), "=r"(r3) : "r"(a))

#define MMA_BF16(d, a, b0r, b1r) \
    asm volatile("mma.sync.aligned.m16n8k16.row.col.f32.bf16.bf16.f32 " \
                 "{%0,%1,%2,%3},{%4,%5,%6,%7},{%8,%9},{%0,%1,%2,%3};" \
                 : "+f"((d)[0]), "+f"((d)[1]), "+f"((d)[2]), "+f"((d)[3]) \
                 : "r"((a)[0]), "r"((a)[1]), "r"((a)[2]), "r"((a)[3]), \
                   "r"(b0r), "r"(b1r))

// tile = 128 rows x 16 halfs (32B/row), 4 KB. Two 16B chunks per row,
// XOR-swizzled: chunk' = chunk ^ ((row ^ row>>2) & 1)  -> conflict-free
// for both quarter-warp STS.128 phases and all ldmatrix 8-addr phases.
__device__ __forceinline__ uint32_t tswz(int row, int c) {
    return (uint32_t)(row * 32 + ((c ^ ((row ^ (row >> 2)) & 1)) << 4));
}

#define TILE_BYTES 4096
#define STAGE_BYTES (4 * TILE_BYTES)   // Ah, Al, Bh, Bl

__global__ __launch_bounds__(256) void k_mma(float* __restrict__ out) {
    __shared__ __align__(128) char smem[2 * STAGE_BYTES];   // 32 KB
    const uint32_t sbase = (uint32_t)__cvta_generic_to_shared(smem);

    const int tid = threadIdx.x;
    const int wid = tid >> 5, lane = tid & 31;
    const int warp_m = wid & 3;     // 0..3  -> M rows warp_m*32
    const int warp_n = wid >> 2;    // 0..1  -> N cols warp_n*64
    const int bn = blockIdx.x;      // 0..31
    const int bm = blockIdx.y;      // 0..3

    // Staging: thread -> row = tid>>1 (0..127), chunk c = tid&1 (k-half)
    const int srow = tid >> 1, sc = tid & 1;
    const __nv_bfloat16* gAh = g_Ah + (size_t)(bm * 128 + srow) * C3K + sc * 8;
    const __nv_bfloat16* gAl = g_Al + (size_t)(bm * 128 + srow) * C3K + sc * 8;
    const __nv_bfloat16* gBh = g_Bh + (size_t)(bn * 128 + srow) * C3K + sc * 8;
    const __nv_bfloat16* gBl = g_Bl + (size_t)(bn * 128 + srow) * C3K + sc * 8;
    const uint32_t soff = tswz(srow, sc);   // same slot in every tile

    // ldmatrix per-lane tile-relative offsets
    // A (mf = 0,1): row = warp_m*32 + mf*16 + (lane&15), chunk = lane>>4
    uint32_t offA[2];
#pragma unroll
    for (int mf = 0; mf < 2; mf++)
        offA[mf] = tswz(warp_m * 32 + mf * 16 + (lane & 15), lane >> 4);
    // B (ng = 0..3): row = warp_n*64 + ng*16 + ((lane>>4)<<3) + (lane&7),
    //                chunk = (lane>>3)&1
    uint32_t offB[4];
#pragma unroll
    for (int ng = 0; ng < 4; ng++)
        offB[ng] = tswz(warp_n * 64 + ng * 16 + ((lane >> 4) << 3) + (lane & 7),
                        (lane >> 3) & 1);

    float acc[2][8][4];
#pragma unroll
    for (int mf = 0; mf < 2; mf++)
#pragma unroll
        for (int nf = 0; nf < 8; nf++)
#pragma unroll
            for (int r = 0; r < 4; r++) acc[mf][nf][r] = 0.f;

    // Prologue: k-tile 0 -> stage 0
    {
        uint4 vah = *(const uint4*)gAh;
        uint4 val = *(const uint4*)gAl;
        uint4 vbh = *(const uint4*)gBh;
        uint4 vbl = *(const uint4*)gBl;
        char* st = smem;
        *(uint4*)(st + 0 * TILE_BYTES + soff) = vah;
        *(uint4*)(st + 1 * TILE_BYTES + soff) = val;
        *(uint4*)(st + 2 * TILE_BYTES + soff) = vbh;
        *(uint4*)(st + 3 * TILE_BYTES + soff) = vbl;
    }
    __syncthreads();

    for (int kt = 0; kt < NKT16; kt++) {
        const int s = kt & 1;
        const uint32_t stg = sbase + s * STAGE_BYTES;

        // Prefetch next k-tile
        uint4 vah, val, vbh, vbl;
        const bool more = (kt + 1 < NKT16);
        if (more) {
            vah = *(const uint4*)(gAh + (kt + 1) * 16);
            val = *(const uint4*)(gAl + (kt + 1) * 16);
            vbh = *(const uint4*)(gBh + (kt + 1) * 16);
            vbl = *(const uint4*)(gBl + (kt + 1) * 16);
        }

        // Load fragments
        uint32_t ah[2][4], al[2][4], bh[4][4], bl[4][4];
#pragma unroll
        for (int mf = 0; mf < 2; mf++) {
            LDSM_X4(ah[mf][0], ah[mf][1], ah[mf][2], ah[mf][3],
                    stg + 0 * TILE_BYTES + offA[mf]);
            LDSM_X4(al[mf][0], al[mf][1], al[mf][2], al[mf][3],
                    stg + 1 * TILE_BYTES + offA[mf]);
        }
#pragma unroll
        for (int ng = 0; ng < 4; ng++) {
            LDSM_X4(bh[ng][0], bh[ng][1], bh[ng][2], bh[ng][3],
                    stg + 2 * TILE_BYTES + offB[ng]);
            LDSM_X4(bl[ng][0], bl[ng][1], bl[ng][2], bl[ng][3],
                    stg + 3 * TILE_BYTES + offB[ng]);
        }

        // 3 product passes: Ah*Bh, Ah*Bl, Al*Bh
#pragma unroll
        for (int mf = 0; mf < 2; mf++) {
#pragma unroll
            for (int nf = 0; nf < 8; nf++) {
                const int ng = nf >> 1, hb = (nf & 1) * 2;
                MMA_BF16(acc[mf][nf], ah[mf], bh[ng][hb], bh[ng][hb + 1]);
                MMA_BF16(acc[mf][nf], ah[mf], bl[ng][hb], bl[ng][hb + 1]);
                MMA_BF16(acc[mf][nf], al[mf], bh[ng][hb], bh[ng][hb + 1]);
            }
        }

        // Store prefetched tile into the other stage
        if (more) {
            char* st = smem + (s ^ 1) * STAGE_BYTES;
            *(uint4*)(st + 0 * TILE_BYTES + soff) = vah;
            *(uint4*)(st + 1 * TILE_BYTES + soff) = val;
            *(uint4*)(st + 2 * TILE_BYTES + soff) = vbh;
            *(uint4*)(st + 3 * TILE_BYTES + soff) = vbl;
        }
        __syncthreads();
    }

    // Epilogue: d0,d1 -> (m = l>>2, n = 2(l&3)); d2,d3 -> m+8
    const int mbase = bm * 128 + warp_m * 32 + (lane >> 2);
    const int nbase = bn * 128 + warp_n * 64 + 2 * (lane & 3);
#pragma unroll
    for (int mf = 0; mf < 2; mf++) {
#pragma unroll
        for (int nf = 0; nf < 8; nf++) {
            const int m = mbase + mf * 16;
            const int n = nbase + nf * 8;
            *(float2*)(out + (size_t)m * DOUT + n) =
                make_float2(acc[mf][nf][0], acc[mf][nf][1]);
            *(float2*)(out + (size_t)(m + 8) * DOUT + n) =
                make_float2(acc[mf][nf][2], acc[mf][nf][3]);
        }
    }
}

// ---------------------------------------------------------------------------
// Launch
// ---------------------------------------------------------------------------
extern "C" void kernel_launch(void* const* d_in, const int* in_sizes, int n_in,
                              void* d_out, int out_size) {
    const float* x     = (const float*)d_in[0];
    const float* Wemb  = (const float*)d_in[1];
    const float* bemb  = (const float*)d_in[2];
    const float* gamma = (const float*)d_in[3];
    const float* beta  = (const float*)d_in[4];
    const float* Wfc2  = (const float*)d_in[5];
    float* out = (float*)d_out;

    k_convB<<<2048, 256>>>(Wfc2);
    k_embed<<<1184, 256>>>(x, Wemb, bemb);
    k_stats<<<96, 256>>>();
    k_final<<<1, 32>>>(gamma, beta);
    k_convA<<<192, 256>>>();
    k_mma<<<dim3(32, 4), 256>>>(out);
}

// round 7
// speedup vs baseline: 1.7557x; 1.0718x over previous
#include <cuda_runtime.h>
#include <cuda_bf16.h>
#include <cstdint>
#include <cstddef>

// Problem constants
#define BB   512
#define KK   512
#define DIN  1024
#define DOUT 4096
#define C3K  1536          // 3*K
#define NROWS (BB*KK)      // 262144
#define NIT   (C3K/32)     // 48 k32-iterations

// Scratch (static device globals — no allocation)
__device__ float g_y[BB * C3K];     // [b][o*512 + k], 3 MB
__device__ float g_stats[6];
__device__ float g_coef[6];
__device__ int   g_cnt;
__device__ __align__(16) __nv_bfloat16 g_Ah[BB * C3K];
__device__ __align__(16) __nv_bfloat16 g_Al[BB * C3K];
__device__ __align__(16) __nv_bfloat16 g_Bh[DOUT * C3K];
__device__ __align__(16) __nv_bfloat16 g_Bl[DOUT * C3K];

// ---------------------------------------------------------------------------
// Kernel A: y = x @ W_emb^T + b. One warp per row, W_emb register-resident.
// ---------------------------------------------------------------------------
__global__ __launch_bounds__(256) void k_embed(const float* __restrict__ x,
                                               const float* __restrict__ Wemb,
                                               const float* __restrict__ bemb) {
    const int tid = threadIdx.x;
    if (blockIdx.x == 0 && tid < 6) g_stats[tid] = 0.0f;
    const int lane = tid & 31;

    float4 w0[8], w1[8], w2[8];
    const float4* W4 = (const float4*)Wemb;
#pragma unroll
    for (int j = 0; j < 8; j++) {
        w0[j] = W4[      j * 32 + lane];
        w1[j] = W4[256 + j * 32 + lane];
        w2[j] = W4[512 + j * 32 + lane];
    }
    const float b0 = bemb[0], b1 = bemb[1], b2 = bemb[2];

    int gw = blockIdx.x * 8 + (tid >> 5);
    const int nw = gridDim.x * 8;
    for (int row = gw; row < NROWS; row += nw) {
        const float4* xr = (const float4*)x + (size_t)row * 256;
        float a0 = 0.f, a1 = 0.f, a2 = 0.f;
#pragma unroll
        for (int j = 0; j < 8; j++) {
            float4 xv = xr[j * 32 + lane];
            a0 += xv.x * w0[j].x + xv.y * w0[j].y + xv.z * w0[j].z + xv.w * w0[j].w;
            a1 += xv.x * w1[j].x + xv.y * w1[j].y + xv.z * w1[j].z + xv.w * w1[j].w;
            a2 += xv.x * w2[j].x + xv.y * w2[j].y + xv.z * w2[j].z + xv.w * w2[j].w;
        }
#pragma unroll
        for (int off = 16; off; off >>= 1) {
            a0 += __shfl_xor_sync(0xffffffffu, a0, off);
            a1 += __shfl_xor_sync(0xffffffffu, a1, off);
            a2 += __shfl_xor_sync(0xffffffffu, a2, off);
        }
        if (lane == 0) {
            const int b = row >> 9, k = row & 511;
            float* yb = g_y + (size_t)b * C3K + k;
            yb[0]    = a0 + b0;
            yb[512]  = a1 + b1;
            yb[1024] = a2 + b2;
        }
    }
}

// ---------------------------------------------------------------------------
// k_stats (+fused finalize): per-channel sum/sumsq; the last block computes
// the BN affine coefs and resets the counter.
// ---------------------------------------------------------------------------
__global__ __launch_bounds__(256) void k_stats(const float* __restrict__ gamma,
                                               const float* __restrict__ beta) {
    float s[3] = {0.f, 0.f, 0.f};
    float q[3] = {0.f, 0.f, 0.f};
    const int stride = gridDim.x * blockDim.x;
    const float4* y4 = (const float4*)g_y;
    const int n4 = (BB * C3K) / 4;
    for (int i = blockIdx.x * blockDim.x + threadIdx.x; i < n4; i += stride) {
        const int o = (i % 384) >> 7;
        float4 v = y4[i];
        s[o] += v.x + v.y + v.z + v.w;
        q[o] += v.x * v.x + v.y * v.y + v.z * v.z + v.w * v.w;
    }
#pragma unroll
    for (int off = 16; off; off >>= 1) {
#pragma unroll
        for (int o = 0; o < 3; o++) {
            s[o] += __shfl_xor_sync(0xffffffffu, s[o], off);
            q[o] += __shfl_xor_sync(0xffffffffu, q[o], off);
        }
    }
    __shared__ float rs[6];
    __shared__ int is_last;
    if (threadIdx.x < 6) rs[threadIdx.x] = 0.f;
    __syncthreads();
    if ((threadIdx.x & 31) == 0) {
#pragma unroll
        for (int o = 0; o < 3; o++) {
            atomicAdd(&rs[o], s[o]);
            atomicAdd(&rs[3 + o], q[o]);
        }
    }
    __syncthreads();
    if (threadIdx.x < 6) atomicAdd(&g_stats[threadIdx.x], rs[threadIdx.x]);
    if (threadIdx.x == 0) {
        __threadfence();
        int old = atomicAdd(&g_cnt, 1);
        is_last = (old == (int)gridDim.x - 1) ? 1 : 0;
    }
    __syncthreads();
    if (is_last && threadIdx.x == 0) {
        __threadfence();
        const float n = (float)NROWS;
#pragma unroll
        for (int o = 0; o < 3; o++) {
            float sm = atomicAdd(&g_stats[o], 0.0f);
            float sq = atomicAdd(&g_stats[3 + o], 0.0f);
            float mean = sm / n;
            float var  = sq / n - mean * mean;
            float sc   = gamma[o] * rsqrtf(var + 1e-5f);
            g_coef[o]     = sc;
            g_coef[3 + o] = beta[o] - mean * sc;
        }
        g_cnt = 0;
    }
}

// ---------------------------------------------------------------------------
// convA: normalize g_y and split into bf16 hi/lo
// ---------------------------------------------------------------------------
__global__ __launch_bounds__(256) void k_convA() {
    const int n4 = (BB * C3K) / 4;
    const int stride = gridDim.x * blockDim.x;
    const float4* y4 = (const float4*)g_y;
    for (int i = blockIdx.x * blockDim.x + threadIdx.x; i < n4; i += stride) {
        const int o = (i % 384) >> 7;
        const float sc = g_coef[o], sh = g_coef[3 + o];
        float4 v = y4[i];
        float a[4] = {v.x * sc + sh, v.y * sc + sh, v.z * sc + sh, v.w * sc + sh};
        __nv_bfloat16 h[4], l[4];
#pragma unroll
        for (int j = 0; j < 4; j++) {
            h[j] = __float2bfloat16_rn(a[j]);
            l[j] = __float2bfloat16_rn(a[j] - __bfloat162float(h[j]));
        }
        ((__nv_bfloat162*)g_Ah)[i * 2 + 0] = __nv_bfloat162(h[0], h[1]);
        ((__nv_bfloat162*)g_Ah)[i * 2 + 1] = __nv_bfloat162(h[2], h[3]);
        ((__nv_bfloat162*)g_Al)[i * 2 + 0] = __nv_bfloat162(l[0], l[1]);
        ((__nv_bfloat162*)g_Al)[i * 2 + 1] = __nv_bfloat162(l[2], l[3]);
    }
}

// ---------------------------------------------------------------------------
// convB: split W_fc2 into bf16 hi/lo
// ---------------------------------------------------------------------------
__global__ __launch_bounds__(256) void k_convB(const float* __restrict__ W) {
    const int n4 = (DOUT * C3K) / 4;
    const int stride = gridDim.x * blockDim.x;
    const float4* w4 = (const float4*)W;
    for (int i = blockIdx.x * blockDim.x + threadIdx.x; i < n4; i += stride) {
        float4 v = w4[i];
        float a[4] = {v.x, v.y, v.z, v.w};
        __nv_bfloat16 h[4], l[4];
#pragma unroll
        for (int j = 0; j < 4; j++) {
            h[j] = __float2bfloat16_rn(a[j]);
            l[j] = __float2bfloat16_rn(a[j] - __bfloat162float(h[j]));
        }
        ((__nv_bfloat162*)g_Bh)[i * 2 + 0] = __nv_bfloat162(h[0], h[1]);
        ((__nv_bfloat162*)g_Bh)[i * 2 + 1] = __nv_bfloat162(h[2], h[3]);
        ((__nv_bfloat162*)g_Bl)[i * 2 + 0] = __nv_bfloat162(l[0], l[1]);
        ((__nv_bfloat162*)g_Bl)[i * 2 + 1] = __nv_bfloat162(l[2], l[3]);
    }
}

// ---------------------------------------------------------------------------
// k_mma: out = A @ B^T via mma.sync m16n8k16 bf16, 3-product split.
// CTA 128x128, 8 warps 32Mx64N. K-iter 32, 3-stage cp.async ring.
// ---------------------------------------------------------------------------
#define LDSM_X4(r0, r1, r2, r3, a) \
    asm volatile("ldmatrix.sync.aligned.m8n8.x4.shared.b16 {%0,%1,%2,%3}, [%4];" \
                 : "=r"(r0), "=r"(r1), "=r"(r2), "=r"(r3) : "r"(a))

#define MMA_BF16(d, a, b0r, b1r) \
    asm volatile("mma.sync.aligned.m16n8k16.row.col.f32.bf16.bf16.f32 " \
                 "{%0,%1,%2,%3},{%4,%5,%6,%7},{%8,%9},{%0,%1,%2,%3};" \
                 : "+f"((d)[0]), "+f"((d)[1]), "+f"((d)[2]), "+f"((d)[3]) \
                 : "r"((a)[0]), "r"((a)[1]), "r"((a)[2]), "r"((a)[3]), \
                   "r"(b0r), "r"(b1r))

__device__ __forceinline__ void cpa16(uint32_t dst, const void* src) {
    asm volatile("cp.async.cg.shared.global [%0], [%1], 16;" :: "r"(dst), "l"(src));
}
#define CPA_COMMIT() asm volatile("cp.async.commit_group;" ::: "memory")
#define CPA_WAIT1()  asm volatile("cp.async.wait_group 1;" ::: "memory")
#define CPA_WAIT0()  asm volatile("cp.async.wait_group 0;" ::: "memory")

// tile = 128 rows x 32 halfs (64B/row) = 8 KB; 4 x 16B chunks per row.
// chunk' = c ^ ((row ^ row>>2) & 3): conflict-free for all ldmatrix phases.
__device__ __forceinline__ uint32_t tswz(int row, int c) {
    return (uint32_t)(row * 64 + ((c ^ ((row ^ (row >> 2)) & 3)) << 4));
}

#define TILE_B  8192
#define STAGE_B (4 * TILE_B)           // Ah, Al, Bh, Bl
#define SMEM_B  (3 * STAGE_B)          // 98304

__global__ __launch_bounds__(256, 1) void k_mma(float* __restrict__ out) {
    extern __shared__ __align__(128) char smem[];
    const uint32_t sbase = (uint32_t)__cvta_generic_to_shared(smem);

    const int tid = threadIdx.x;
    const int wid = tid >> 5, lane = tid & 31;
    const int warp_m = wid & 3;
    const int warp_n = wid >> 2;
    const int bn = blockIdx.x;      // 0..31
    const int bm = blockIdx.y;      // 0..3

    // Staging: thread -> row = tid>>1, chunks {2c, 2c+1} where c = tid&1
    const int srow = tid >> 1, sc0 = (tid & 1) * 2;
    const __nv_bfloat16* gsrc[4] = {
        g_Ah + (size_t)(bm * 128 + srow) * C3K + sc0 * 8,
        g_Al + (size_t)(bm * 128 + srow) * C3K + sc0 * 8,
        g_Bh + (size_t)(bn * 128 + srow) * C3K + sc0 * 8,
        g_Bl + (size_t)(bn * 128 + srow) * C3K + sc0 * 8};
    const uint32_t soff0 = tswz(srow, sc0);
    const uint32_t soff1 = tswz(srow, sc0 + 1);

    // ldmatrix per-lane tile-relative offsets, per k16 sub-step j
    uint32_t offA[2][2], offB[4][2];
#pragma unroll
    for (int mf = 0; mf < 2; mf++)
#pragma unroll
        for (int j = 0; j < 2; j++)
            offA[mf][j] = tswz(warp_m * 32 + mf * 16 + (lane & 15),
                               2 * j + (lane >> 4));
#pragma unroll
    for (int ng = 0; ng < 4; ng++)
#pragma unroll
        for (int j = 0; j < 2; j++)
            offB[ng][j] = tswz(warp_n * 64 + ng * 16 + ((lane >> 4) << 3) + (lane & 7),
                               2 * j + ((lane >> 3) & 1));

    float acc[2][8][4];
#pragma unroll
    for (int mf = 0; mf < 2; mf++)
#pragma unroll
        for (int nf = 0; nf < 8; nf++)
#pragma unroll
            for (int r = 0; r < 4; r++) acc[mf][nf][r] = 0.f;

    // Issue one stage's cp.async group (iteration it -> stage it%3)
    auto issue = [&](int it) {
        const uint32_t st = sbase + (it % 3) * STAGE_B;
        const int koff = it * 32;
#pragma unroll
        for (int t = 0; t < 4; t++) {
            const __nv_bfloat16* s = gsrc[t] + koff;
            cpa16(st + t * TILE_B + soff0, s);
            cpa16(st + t * TILE_B + soff1, s + 8);
        }
        CPA_COMMIT();
    };

    issue(0);
    issue(1);

    for (int it = 0; it < NIT; it++) {
        if (it + 2 < NIT) CPA_WAIT1(); else CPA_WAIT0();
        __syncthreads();
        if (it + 2 < NIT) issue(it + 2);

        const uint32_t stg = sbase + (it % 3) * STAGE_B;
#pragma unroll
        for (int j = 0; j < 2; j++) {
            uint32_t ah[2][4], al[2][4], bh[4][4], bl[4][4];
#pragma unroll
            for (int mf = 0; mf < 2; mf++) {
                LDSM_X4(ah[mf][0], ah[mf][1], ah[mf][2], ah[mf][3],
                        stg + 0 * TILE_B + offA[mf][j]);
                LDSM_X4(al[mf][0], al[mf][1], al[mf][2], al[mf][3],
                        stg + 1 * TILE_B + offA[mf][j]);
            }
#pragma unroll
            for (int ng = 0; ng < 4; ng++) {
                LDSM_X4(bh[ng][0], bh[ng][1], bh[ng][2], bh[ng][3],
                        stg + 2 * TILE_B + offB[ng][j]);
                LDSM_X4(bl[ng][0], bl[ng][1], bl[ng][2], bl[ng][3],
                        stg + 3 * TILE_B + offB[ng][j]);
            }
#pragma unroll
            for (int mf = 0; mf < 2; mf++) {
#pragma unroll
                for (int nf = 0; nf < 8; nf++) {
                    const int ng = nf >> 1, hb = (nf & 1) * 2;
                    MMA_BF16(acc[mf][nf], ah[mf], bh[ng][hb], bh[ng][hb + 1]);
                    MMA_BF16(acc[mf][nf], ah[mf], bl[ng][hb], bl[ng][hb + 1]);
                    MMA_BF16(acc[mf][nf], al[mf], bh[ng][hb], bh[ng][hb + 1]);
                }
            }
        }
        __syncthreads();
    }

    // Epilogue
    const int mbase = bm * 128 + warp_m * 32 + (lane >> 2);
    const int nbase = bn * 128 + warp_n * 64 + 2 * (lane & 3);
#pragma unroll
    for (int mf = 0; mf < 2; mf++) {
#pragma unroll
        for (int nf = 0; nf < 8; nf++) {
            const int m = mbase + mf * 16;
            const int n = nbase + nf * 8;
            *(float2*)(out + (size_t)m * DOUT + n) =
                make_float2(acc[mf][nf][0], acc[mf][nf][1]);
            *(float2*)(out + (size_t)(m + 8) * DOUT + n) =
                make_float2(acc[mf][nf][2], acc[mf][nf][3]);
        }
    }
}

// ---------------------------------------------------------------------------
// Launch
// ---------------------------------------------------------------------------
extern "C" void kernel_launch(void* const* d_in, const int* in_sizes, int n_in,
                              void* d_out, int out_size) {
    const float* x     = (const float*)d_in[0];
    const float* Wemb  = (const float*)d_in[1];
    const float* bemb  = (const float*)d_in[2];
    const float* gamma = (const float*)d_in[3];
    const float* beta  = (const float*)d_in[4];
    const float* Wfc2  = (const float*)d_in[5];
    float* out = (float*)d_out;

    static int smem_set = 0;
    if (!smem_set) {
        cudaFuncSetAttribute(k_mma, cudaFuncAttributeMaxDynamicSharedMemorySize, SMEM_B);
        smem_set = 1;
    }

    k_convB<<<2048, 256>>>(Wfc2);
    k_embed<<<1184, 256>>>(x, Wemb, bemb);
    k_stats<<<96, 256>>>(gamma, beta);
    k_convA<<<192, 256>>>();
    k_mma<<<dim3(32, 4), 256, SMEM_B>>>(out);
}

// round 8
// speedup vs baseline: 1.7842x; 1.0162x over previous
#include <cuda_runtime.h>
#include <cuda_bf16.h>
#include <cstdint>
#include <cstddef>

// Problem constants
#define BB   512
#define KK   512
#define DIN  1024
#define DOUT 4096
#define C3K  1536          // 3*K
#define NROWS (BB*KK)      // 262144
#define NIT   (C3K/32)     // 48 k32-iterations

// Scratch (static device globals — no allocation)
__device__ float g_stats[6];
__device__ float g_coef[6];        // scale[3], shift[3]
__device__ float g_bias[DOUT];     // sum_c shift_c * rowsum_c(W)
__device__ int   g_cnt;
__device__ __align__(16) __nv_bfloat16 g_Ah[BB * C3K];    // hi(raw y)
__device__ __align__(16) __nv_bfloat16 g_Al[BB * C3K];    // lo(raw y)
__device__ __align__(16) __nv_bfloat16 g_Bh[DOUT * C3K];  // hi(sc_c * W)
__device__ __align__(16) __nv_bfloat16 g_Bl[DOUT * C3K];  // lo(sc_c * W)

// ---------------------------------------------------------------------------
// Kernel A: y = x @ W_emb^T + b, written directly as bf16 hi/lo split (raw y).
// One warp per row, W_emb register-resident.
// ---------------------------------------------------------------------------
__global__ __launch_bounds__(256) void k_embed(const float* __restrict__ x,
                                               const float* __restrict__ Wemb,
                                               const float* __restrict__ bemb) {
    const int tid = threadIdx.x;
    if (blockIdx.x == 0 && tid < 6) g_stats[tid] = 0.0f;
    const int lane = tid & 31;

    float4 w0[8], w1[8], w2[8];
    const float4* W4 = (const float4*)Wemb;
#pragma unroll
    for (int j = 0; j < 8; j++) {
        w0[j] = W4[      j * 32 + lane];
        w1[j] = W4[256 + j * 32 + lane];
        w2[j] = W4[512 + j * 32 + lane];
    }
    const float b0 = bemb[0], b1 = bemb[1], b2 = bemb[2];

    int gw = blockIdx.x * 8 + (tid >> 5);
    const int nw = gridDim.x * 8;
    for (int row = gw; row < NROWS; row += nw) {
        const float4* xr = (const float4*)x + (size_t)row * 256;
        float a0 = 0.f, a1 = 0.f, a2 = 0.f;
#pragma unroll
        for (int j = 0; j < 8; j++) {
            float4 xv = xr[j * 32 + lane];
            a0 += xv.x * w0[j].x + xv.y * w0[j].y + xv.z * w0[j].z + xv.w * w0[j].w;
            a1 += xv.x * w1[j].x + xv.y * w1[j].y + xv.z * w1[j].z + xv.w * w1[j].w;
            a2 += xv.x * w2[j].x + xv.y * w2[j].y + xv.z * w2[j].z + xv.w * w2[j].w;
        }
#pragma unroll
        for (int off = 16; off; off >>= 1) {
            a0 += __shfl_xor_sync(0xffffffffu, a0, off);
            a1 += __shfl_xor_sync(0xffffffffu, a1, off);
            a2 += __shfl_xor_sync(0xffffffffu, a2, off);
        }
        if (lane == 0) {
            const int b = row >> 9, k = row & 511;
            const size_t base = (size_t)b * C3K + k;
            const float yv[3] = {a0 + b0, a1 + b1, a2 + b2};
#pragma unroll
            for (int o = 0; o < 3; o++) {
                __nv_bfloat16 h = __float2bfloat16_rn(yv[o]);
                __nv_bfloat16 l = __float2bfloat16_rn(yv[o] - __bfloat162float(h));
                g_Ah[base + o * 512] = h;
                g_Al[base + o * 512] = l;
            }
        }
    }
}

// ---------------------------------------------------------------------------
// k_stats (+fused finalize): per-channel sum/sumsq over y = Ah + Al;
// last block computes BN affine coefs and resets the counter.
// ---------------------------------------------------------------------------
__global__ __launch_bounds__(256) void k_stats(const float* __restrict__ gamma,
                                               const float* __restrict__ beta) {
    float s[3] = {0.f, 0.f, 0.f};
    float q[3] = {0.f, 0.f, 0.f};
    const int stride = gridDim.x * blockDim.x;
    const uint4* h4 = (const uint4*)g_Ah;
    const uint4* l4 = (const uint4*)g_Al;
    const int n8 = (BB * C3K) / 8;   // 98304 uint4 (8 bf16 each)
    for (int i = blockIdx.x * blockDim.x + threadIdx.x; i < n8; i += stride) {
        const int o = (i % 192) >> 6;   // ((i*8) % 1536) / 512
        uint4 hv = h4[i], lv = l4[i];
#pragma unroll
        for (int w = 0; w < 4; w++) {
            __nv_bfloat162 hp = *(__nv_bfloat162*)&((&hv.x)[w]);
            __nv_bfloat162 lp = *(__nv_bfloat162*)&((&lv.x)[w]);
            float y0 = __bfloat162float(hp.x) + __bfloat162float(lp.x);
            float y1 = __bfloat162float(hp.y) + __bfloat162float(lp.y);
            s[o] += y0 + y1;
            q[o] += y0 * y0 + y1 * y1;
        }
    }
#pragma unroll
    for (int off = 16; off; off >>= 1) {
#pragma unroll
        for (int o = 0; o < 3; o++) {
            s[o] += __shfl_xor_sync(0xffffffffu, s[o], off);
            q[o] += __shfl_xor_sync(0xffffffffu, q[o], off);
        }
    }
    __shared__ float rs[6];
    __shared__ int is_last;
    if (threadIdx.x < 6) rs[threadIdx.x] = 0.f;
    __syncthreads();
    if ((threadIdx.x & 31) == 0) {
#pragma unroll
        for (int o = 0; o < 3; o++) {
            atomicAdd(&rs[o], s[o]);
            atomicAdd(&rs[3 + o], q[o]);
        }
    }
    __syncthreads();
    if (threadIdx.x < 6) atomicAdd(&g_stats[threadIdx.x], rs[threadIdx.x]);
    if (threadIdx.x == 0) {
        __threadfence();
        int old = atomicAdd(&g_cnt, 1);
        is_last = (old == (int)gridDim.x - 1) ? 1 : 0;
    }
    __syncthreads();
    if (is_last && threadIdx.x == 0) {
        __threadfence();
        const float n = (float)NROWS;
#pragma unroll
        for (int o = 0; o < 3; o++) {
            float sm = atomicAdd(&g_stats[o], 0.0f);
            float sq = atomicAdd(&g_stats[3 + o], 0.0f);
            float mean = sm / n;
            float var  = sq / n - mean * mean;
            float sc   = gamma[o] * rsqrtf(var + 1e-5f);
            g_coef[o]     = sc;
            g_coef[3 + o] = beta[o] - mean * sc;
        }
        g_cnt = 0;
    }
}

// ---------------------------------------------------------------------------
// convB (after stats): Bh/Bl = bf16 split of (sc_c * W), and
// bias[d] = sum_c sh_c * sum_k W[d, c*512+k].  One warp per output row.
// ---------------------------------------------------------------------------
__global__ __launch_bounds__(256) void k_convB(const float* __restrict__ W) {
    const int lane = threadIdx.x & 31;
    const int row = blockIdx.x * 8 + (threadIdx.x >> 5);   // 0..4095
    const float sc[3] = {g_coef[0], g_coef[1], g_coef[2]};
    const float sh[3] = {g_coef[3], g_coef[4], g_coef[5]};

    const float4* wr = (const float4*)(W + (size_t)row * C3K);
    float bias = 0.f;
#pragma unroll
    for (int p = 0; p < 12; p++) {
        const int i = p * 32 + lane;        // float4 index within row (0..383)
        const int o = i >> 7;               // channel: (i*4)/512
        float4 v = wr[i];
        bias += sh[o] * (v.x + v.y + v.z + v.w);
        float a[4] = {v.x * sc[o], v.y * sc[o], v.z * sc[o], v.w * sc[o]};
        __nv_bfloat16 h[4], l[4];
#pragma unroll
        for (int j = 0; j < 4; j++) {
            h[j] = __float2bfloat16_rn(a[j]);
            l[j] = __float2bfloat16_rn(a[j] - __bfloat162float(h[j]));
        }
        const size_t e = (size_t)row * C3K + i * 4;
        *(__nv_bfloat162*)&g_Bh[e]     = __nv_bfloat162(h[0], h[1]);
        *(__nv_bfloat162*)&g_Bh[e + 2] = __nv_bfloat162(h[2], h[3]);
        *(__nv_bfloat162*)&g_Bl[e]     = __nv_bfloat162(l[0], l[1]);
        *(__nv_bfloat162*)&g_Bl[e + 2] = __nv_bfloat162(l[2], l[3]);
    }
#pragma unroll
    for (int off = 16; off; off >>= 1)
        bias += __shfl_xor_sync(0xffffffffu, bias, off);
    if (lane == 0) g_bias[row] = bias;
}

// ---------------------------------------------------------------------------
// k_mma: out = y @ (sc*W)^T + bias, mma.sync m16n8k16 bf16 3-product split.
// CTA 128x128, 8 warps 32Mx64N. K-iter 32, 4-stage cp.async ring, 1 sync/iter.
// ---------------------------------------------------------------------------
#define LDSM_X4(r0, r1, r2, r3, a) \
    asm volatile("ldmatrix.sync.aligned.m8n8.x4.shared.b16 {%0,%1,%2,%3}, [%4];" \
                 : "=r"(r0), "=r"(r1), "=r"(r2), "=r"(r3) : "r"(a))

#define MMA_BF16(d, a, b0r, b1r) \
    asm volatile("mma.sync.aligned.m16n8k16.row.col.f32.bf16.bf16.f32 " \
                 "{%0,%1,%2,%3},{%4,%5,%6,%7},{%8,%9},{%0,%1,%2,%3};" \
                 : "+f"((d)[0]), "+f"((d)[1]), "+f"((d)[2]), "+f"((d)[3]) \
                 : "r"((a)[0]), "r"((a)[1]), "r"((a)[2]), "r"((a)[3]), \
                   "r"(b0r), "r"(b1r))

__device__ __forceinline__ void cpa16(uint32_t dst, const void* src) {
    asm volatile("cp.async.cg.shared.global [%0], [%1], 16;" :: "r"(dst), "l"(src));
}
#define CPA_COMMIT() asm volatile("cp.async.commit_group;" ::: "memory")
#define CPA_WAIT(n)  asm volatile("cp.async.wait_group %0;" :: "n"(n) : "memory")

// tile = 128 rows x 32 halfs (64B/row) = 8 KB; 4 x 16B chunks per row.
__device__ __forceinline__ uint32_t tswz(int row, int c) {
    return (uint32_t)(row * 64 + ((c ^ ((row ^ (row >> 2)) & 3)) << 4));
}

#define TILE_B  8192
#define STAGE_B (4 * TILE_B)           // Ah, Al, Bh, Bl
#define SMEM_B  (4 * STAGE_B)          // 4-stage ring: 131072

__global__ __launch_bounds__(256, 1) void k_mma(float* __restrict__ out) {
    extern __shared__ __align__(128) char smem[];
    const uint32_t sbase = (uint32_t)__cvta_generic_to_shared(smem);

    const int tid = threadIdx.x;
    const int wid = tid >> 5, lane = tid & 31;
    const int warp_m = wid & 3;
    const int warp_n = wid >> 2;
    const int bn = blockIdx.x;      // 0..31
    const int bm = blockIdx.y;      // 0..3

    // Staging: thread -> row = tid>>1, chunks {2c, 2c+1} where c = tid&1
    const int srow = tid >> 1, sc0 = (tid & 1) * 2;
    const __nv_bfloat16* gsrc[4] = {
        g_Ah + (size_t)(bm * 128 + srow) * C3K + sc0 * 8,
        g_Al + (size_t)(bm * 128 + srow) * C3K + sc0 * 8,
        g_Bh + (size_t)(bn * 128 + srow) * C3K + sc0 * 8,
        g_Bl + (size_t)(bn * 128 + srow) * C3K + sc0 * 8};
    const uint32_t soff0 = tswz(srow, sc0);
    const uint32_t soff1 = tswz(srow, sc0 + 1);

    uint32_t offA[2][2], offB[4][2];
#pragma unroll
    for (int mf = 0; mf < 2; mf++)
#pragma unroll
        for (int j = 0; j < 2; j++)
            offA[mf][j] = tswz(warp_m * 32 + mf * 16 + (lane & 15),
                               2 * j + (lane >> 4));
#pragma unroll
    for (int ng = 0; ng < 4; ng++)
#pragma unroll
        for (int j = 0; j < 2; j++)
            offB[ng][j] = tswz(warp_n * 64 + ng * 16 + ((lane >> 4) << 3) + (lane & 7),
                               2 * j + ((lane >> 3) & 1));

    float acc[2][8][4];
#pragma unroll
    for (int mf = 0; mf < 2; mf++)
#pragma unroll
        for (int nf = 0; nf < 8; nf++)
#pragma unroll
            for (int r = 0; r < 4; r++) acc[mf][nf][r] = 0.f;

    auto issue = [&](int it) {
        const uint32_t st = sbase + (it & 3) * STAGE_B;
        const int koff = it * 32;
#pragma unroll
        for (int t = 0; t < 4; t++) {
            const __nv_bfloat16* s = gsrc[t] + koff;
            cpa16(st + t * TILE_B + soff0, s);
            cpa16(st + t * TILE_B + soff1, s + 8);
        }
        CPA_COMMIT();
    };

    issue(0); issue(1); issue(2);

    for (int it = 0; it < NIT; it++) {
        // Wait until stage `it` is complete (allow the groups issued after it)
        const int rem = NIT - 1 - it;
        if (rem >= 2) CPA_WAIT(2);
        else if (rem == 1) CPA_WAIT(1);
        else CPA_WAIT(0);
        __syncthreads();                 // single sync per iteration
        if (it + 3 < NIT) issue(it + 3); // writes stage (it-1)&3: already drained

        const uint32_t stg = sbase + (it & 3) * STAGE_B;
#pragma unroll
        for (int j = 0; j < 2; j++) {
            uint32_t ah[2][4], al[2][4], bh[4][4], bl[4][4];
#pragma unroll
            for (int mf = 0; mf < 2; mf++) {
                LDSM_X4(ah[mf][0], ah[mf][1], ah[mf][2], ah[mf][3],
                        stg + 0 * TILE_B + offA[mf][j]);
                LDSM_X4(al[mf][0], al[mf][1], al[mf][2], al[mf][3],
                        stg + 1 * TILE_B + offA[mf][j]);
            }
#pragma unroll
            for (int ng = 0; ng < 4; ng++) {
                LDSM_X4(bh[ng][0], bh[ng][1], bh[ng][2], bh[ng][3],
                        stg + 2 * TILE_B + offB[ng][j]);
                LDSM_X4(bl[ng][0], bl[ng][1], bl[ng][2], bl[ng][3],
                        stg + 3 * TILE_B + offB[ng][j]);
            }
#pragma unroll
            for (int mf = 0; mf < 2; mf++) {
#pragma unroll
                for (int nf = 0; nf < 8; nf++) {
                    const int ng = nf >> 1, hb = (nf & 1) * 2;
                    MMA_BF16(acc[mf][nf], ah[mf], bh[ng][hb], bh[ng][hb + 1]);
                    MMA_BF16(acc[mf][nf], ah[mf], bl[ng][hb], bl[ng][hb + 1]);
                    MMA_BF16(acc[mf][nf], al[mf], bh[ng][hb], bh[ng][hb + 1]);
                }
            }
        }
    }

    // Epilogue (+bias)
    const int mbase = bm * 128 + warp_m * 32 + (lane >> 2);
    const int nbase = bn * 128 + warp_n * 64 + 2 * (lane & 3);
#pragma unroll
    for (int mf = 0; mf < 2; mf++) {
#pragma unroll
        for (int nf = 0; nf < 8; nf++) {
            const int m = mbase + mf * 16;
            const int n = nbase + nf * 8;
            const float bz0 = g_bias[n], bz1 = g_bias[n + 1];
            *(float2*)(out + (size_t)m * DOUT + n) =
                make_float2(acc[mf][nf][0] + bz0, acc[mf][nf][1] + bz1);
            *(float2*)(out + (size_t)(m + 8) * DOUT + n) =
                make_float2(acc[mf][nf][2] + bz0, acc[mf][nf][3] + bz1);
        }
    }
}

// ---------------------------------------------------------------------------
// Launch
// ---------------------------------------------------------------------------
extern "C" void kernel_launch(void* const* d_in, const int* in_sizes, int n_in,
                              void* d_out, int out_size) {
    const float* x     = (const float*)d_in[0];
    const float* Wemb  = (const float*)d_in[1];
    const float* bemb  = (const float*)d_in[2];
    const float* gamma = (const float*)d_in[3];
    const float* beta  = (const float*)d_in[4];
    const float* Wfc2  = (const float*)d_in[5];
    float* out = (float*)d_out;

    static int smem_set = 0;
    if (!smem_set) {
        cudaFuncSetAttribute(k_mma, cudaFuncAttributeMaxDynamicSharedMemorySize, SMEM_B);
        smem_set = 1;
    }

    k_embed<<<1184, 256>>>(x, Wemb, bemb);
    k_stats<<<96, 256>>>(gamma, beta);
    k_convB<<<512, 256>>>(Wfc2);
    k_mma<<<dim3(32, 4), 256, SMEM_B>>>(out);
}

// round 9
// speedup vs baseline: 1.8682x; 1.0471x over previous
#include <cuda_runtime.h>
#include <cuda_bf16.h>
#include <cstdint>
#include <cstddef>

// Problem constants
#define BB   512
#define KK   512
#define DIN  1024
#define DOUT 4096
#define C3K  1536          // 3*K
#define NROWS (BB*KK)      // 262144
#define NIT   (C3K/32)     // 48 k32-iterations

// Scratch (static device globals — no allocation)
__device__ float g_stats[6];
__device__ float g_coef[6];        // scale[3], shift[3]
__device__ float g_bias[DOUT];     // sum_c shift_c * rowsum_c(W)
__device__ int   g_cnt;
__device__ __align__(16) __nv_bfloat16 g_Ah[BB * C3K];    // hi(raw y)
__device__ __align__(16) __nv_bfloat16 g_Al[BB * C3K];    // lo(raw y)
__device__ __align__(16) __nv_bfloat16 g_Bh[DOUT * C3K];  // hi(sc_c * W)
__device__ __align__(16) __nv_bfloat16 g_Bl[DOUT * C3K];  // lo(sc_c * W)

// ---------------------------------------------------------------------------
// Kernel A: y = x @ W_emb^T + b, written directly as bf16 hi/lo split (raw y).
// ---------------------------------------------------------------------------
__global__ __launch_bounds__(256) void k_embed(const float* __restrict__ x,
                                               const float* __restrict__ Wemb,
                                               const float* __restrict__ bemb) {
    const int tid = threadIdx.x;
    if (blockIdx.x == 0 && tid < 6) g_stats[tid] = 0.0f;
    const int lane = tid & 31;

    float4 w0[8], w1[8], w2[8];
    const float4* W4 = (const float4*)Wemb;
#pragma unroll
    for (int j = 0; j < 8; j++) {
        w0[j] = W4[      j * 32 + lane];
        w1[j] = W4[256 + j * 32 + lane];
        w2[j] = W4[512 + j * 32 + lane];
    }
    const float b0 = bemb[0], b1 = bemb[1], b2 = bemb[2];

    int gw = blockIdx.x * 8 + (tid >> 5);
    const int nw = gridDim.x * 8;
    for (int row = gw; row < NROWS; row += nw) {
        const float4* xr = (const float4*)x + (size_t)row * 256;
        float a0 = 0.f, a1 = 0.f, a2 = 0.f;
#pragma unroll
        for (int j = 0; j < 8; j++) {
            float4 xv = xr[j * 32 + lane];
            a0 += xv.x * w0[j].x + xv.y * w0[j].y + xv.z * w0[j].z + xv.w * w0[j].w;
            a1 += xv.x * w1[j].x + xv.y * w1[j].y + xv.z * w1[j].z + xv.w * w1[j].w;
            a2 += xv.x * w2[j].x + xv.y * w2[j].y + xv.z * w2[j].z + xv.w * w2[j].w;
        }
#pragma unroll
        for (int off = 16; off; off >>= 1) {
            a0 += __shfl_xor_sync(0xffffffffu, a0, off);
            a1 += __shfl_xor_sync(0xffffffffu, a1, off);
            a2 += __shfl_xor_sync(0xffffffffu, a2, off);
        }
        if (lane == 0) {
            const int b = row >> 9, k = row & 511;
            const size_t base = (size_t)b * C3K + k;
            const float yv[3] = {a0 + b0, a1 + b1, a2 + b2};
#pragma unroll
            for (int o = 0; o < 3; o++) {
                __nv_bfloat16 h = __float2bfloat16_rn(yv[o]);
                __nv_bfloat16 l = __float2bfloat16_rn(yv[o] - __bfloat162float(h));
                g_Ah[base + o * 512] = h;
                g_Al[base + o * 512] = l;
            }
        }
    }
}

// ---------------------------------------------------------------------------
// k_stats (+fused finalize)
// ---------------------------------------------------------------------------
__global__ __launch_bounds__(256) void k_stats(const float* __restrict__ gamma,
                                               const float* __restrict__ beta) {
    float s[3] = {0.f, 0.f, 0.f};
    float q[3] = {0.f, 0.f, 0.f};
    const int stride = gridDim.x * blockDim.x;
    const uint4* h4 = (const uint4*)g_Ah;
    const uint4* l4 = (const uint4*)g_Al;
    const int n8 = (BB * C3K) / 8;
    for (int i = blockIdx.x * blockDim.x + threadIdx.x; i < n8; i += stride) {
        const int o = (i % 192) >> 6;
        uint4 hv = h4[i], lv = l4[i];
#pragma unroll
        for (int w = 0; w < 4; w++) {
            __nv_bfloat162 hp = *(__nv_bfloat162*)&((&hv.x)[w]);
            __nv_bfloat162 lp = *(__nv_bfloat162*)&((&lv.x)[w]);
            float y0 = __bfloat162float(hp.x) + __bfloat162float(lp.x);
            float y1 = __bfloat162float(hp.y) + __bfloat162float(lp.y);
            s[o] += y0 + y1;
            q[o] += y0 * y0 + y1 * y1;
        }
    }
#pragma unroll
    for (int off = 16; off; off >>= 1) {
#pragma unroll
        for (int o = 0; o < 3; o++) {
            s[o] += __shfl_xor_sync(0xffffffffu, s[o], off);
            q[o] += __shfl_xor_sync(0xffffffffu, q[o], off);
        }
    }
    __shared__ float rs[6];
    __shared__ int is_last;
    if (threadIdx.x < 6) rs[threadIdx.x] = 0.f;
    __syncthreads();
    if ((threadIdx.x & 31) == 0) {
#pragma unroll
        for (int o = 0; o < 3; o++) {
            atomicAdd(&rs[o], s[o]);
            atomicAdd(&rs[3 + o], q[o]);
        }
    }
    __syncthreads();
    if (threadIdx.x < 6) atomicAdd(&g_stats[threadIdx.x], rs[threadIdx.x]);
    if (threadIdx.x == 0) {
        __threadfence();
        int old = atomicAdd(&g_cnt, 1);
        is_last = (old == (int)gridDim.x - 1) ? 1 : 0;
    }
    __syncthreads();
    if (is_last && threadIdx.x == 0) {
        __threadfence();
        const float n = (float)NROWS;
#pragma unroll
        for (int o = 0; o < 3; o++) {
            float sm = atomicAdd(&g_stats[o], 0.0f);
            float sq = atomicAdd(&g_stats[3 + o], 0.0f);
            float mean = sm / n;
            float var  = sq / n - mean * mean;
            float sc   = gamma[o] * rsqrtf(var + 1e-5f);
            g_coef[o]     = sc;
            g_coef[3 + o] = beta[o] - mean * sc;
        }
        g_cnt = 0;
    }
}

// ---------------------------------------------------------------------------
// convB (after stats): Bh/Bl = bf16 split of (sc_c * W); bias per row.
// ---------------------------------------------------------------------------
__global__ __launch_bounds__(256) void k_convB(const float* __restrict__ W) {
    const int lane = threadIdx.x & 31;
    const int row = blockIdx.x * 8 + (threadIdx.x >> 5);
    const float sc[3] = {g_coef[0], g_coef[1], g_coef[2]};
    const float sh[3] = {g_coef[3], g_coef[4], g_coef[5]};

    const float4* wr = (const float4*)(W + (size_t)row * C3K);
    float bias = 0.f;
#pragma unroll
    for (int p = 0; p < 12; p++) {
        const int i = p * 32 + lane;
        const int o = i >> 7;
        float4 v = wr[i];
        bias += sh[o] * (v.x + v.y + v.z + v.w);
        float a[4] = {v.x * sc[o], v.y * sc[o], v.z * sc[o], v.w * sc[o]};
        __nv_bfloat16 h[4], l[4];
#pragma unroll
        for (int j = 0; j < 4; j++) {
            h[j] = __float2bfloat16_rn(a[j]);
            l[j] = __float2bfloat16_rn(a[j] - __bfloat162float(h[j]));
        }
        const size_t e = (size_t)row * C3K + i * 4;
        *(__nv_bfloat162*)&g_Bh[e]     = __nv_bfloat162(h[0], h[1]);
        *(__nv_bfloat162*)&g_Bh[e + 2] = __nv_bfloat162(h[2], h[3]);
        *(__nv_bfloat162*)&g_Bl[e]     = __nv_bfloat162(l[0], l[1]);
        *(__nv_bfloat162*)&g_Bl[e + 2] = __nv_bfloat162(l[2], l[3]);
    }
#pragma unroll
    for (int off = 16; off; off >>= 1)
        bias += __shfl_xor_sync(0xffffffffu, bias, off);
    if (lane == 0) g_bias[row] = bias;
}

// ---------------------------------------------------------------------------
// k_mma: CTA 64(M)x128(N), grid (32,8)=256 CTAs, 2 CTAs/SM.
// 8 warps of 32Mx32N. K-iter 32, 4-stage cp.async ring, 1 sync/iter.
// ---------------------------------------------------------------------------
#define LDSM_X4(r0, r1, r2, r3, a) \
    asm volatile("ldmatrix.sync.aligned.m8n8.x4.shared.b16 {%0,%1,%2,%3}, [%4];" \
                 : "=r"(r0), "=r"(r1), "=r"(r2), "=r"(r3) : "r"(a))

#define MMA_BF16(d, a, b0r, b1r) \
    asm volatile("mma.sync.aligned.m16n8k16.row.col.f32.bf16.bf16.f32 " \
                 "{%0,%1,%2,%3},{%4,%5,%6,%7},{%8,%9},{%0,%1,%2,%3};" \
                 : "+f"((d)[0]), "+f"((d)[1]), "+f"((d)[2]), "+f"((d)[3]) \
                 : "r"((a)[0]), "r"((a)[1]), "r"((a)[2]), "r"((a)[3]), \
                   "r"(b0r), "r"(b1r))

__device__ __forceinline__ void cpa16(uint32_t dst, const void* src) {
    asm volatile("cp.async.cg.shared.global [%0], [%1], 16;" :: "r"(dst), "l"(src));
}
#define CPA_COMMIT() asm volatile("cp.async.commit_group;" ::: "memory")
#define CPA_WAIT(n)  asm volatile("cp.async.wait_group %0;" :: "n"(n) : "memory")

// row stride 64B, 4 x 16B chunks, XOR swizzle (proven conflict-free R7/R8)
__device__ __forceinline__ uint32_t tswz(int row, int c) {
    return (uint32_t)(row * 64 + ((c ^ ((row ^ (row >> 2)) & 3)) << 4));
}

#define TILE_A   4096                    // 64 rows x 64 B
#define TILE_BB  8192                    // 128 rows x 64 B
#define STAGE_B  (2 * TILE_A + 2 * TILE_BB)   // Ah, Al, Bh, Bl = 24576
#define SMEM_B   (4 * STAGE_B)                // 98304

__global__ __launch_bounds__(256, 2) void k_mma(float* __restrict__ out) {
    extern __shared__ __align__(128) char smem[];
    const uint32_t sbase = (uint32_t)__cvta_generic_to_shared(smem);

    const int tid = threadIdx.x;
    const int wid = tid >> 5, lane = tid & 31;
    const int warp_m = wid & 1;       // 0..1 -> 32 M rows
    const int warp_n = wid >> 1;      // 0..3 -> 32 N cols
    const int bn = blockIdx.x;        // 0..31
    const int bm = blockIdx.y;        // 0..7 (64 rows each)

    // Staging: thread -> row = tid>>2 (0..63), chunk = tid&3
    const int srow = tid >> 2, scn = tid & 3;
    const __nv_bfloat16* gA[2] = {
        g_Ah + (size_t)(bm * 64 + srow) * C3K + scn * 8,
        g_Al + (size_t)(bm * 64 + srow) * C3K + scn * 8};
    const __nv_bfloat16* gB[2] = {
        g_Bh + (size_t)(bn * 128 + srow) * C3K + scn * 8,
        g_Bl + (size_t)(bn * 128 + srow) * C3K + scn * 8};
    const uint32_t soffA  = tswz(srow, scn);
    const uint32_t soffB0 = tswz(srow, scn);
    const uint32_t soffB1 = tswz(srow + 64, scn);
    const size_t bstride64 = (size_t)64 * C3K;

    uint32_t offA[2][2], offB[2][2];
#pragma unroll
    for (int mf = 0; mf < 2; mf++)
#pragma unroll
        for (int j = 0; j < 2; j++)
            offA[mf][j] = tswz(warp_m * 32 + mf * 16 + (lane & 15),
                               2 * j + (lane >> 4));
#pragma unroll
    for (int ng = 0; ng < 2; ng++)
#pragma unroll
        for (int j = 0; j < 2; j++)
            offB[ng][j] = tswz(warp_n * 32 + ng * 16 + ((lane >> 4) << 3) + (lane & 7),
                               2 * j + ((lane >> 3) & 1));

    float acc[2][4][4];
#pragma unroll
    for (int mf = 0; mf < 2; mf++)
#pragma unroll
        for (int nf = 0; nf < 4; nf++)
#pragma unroll
            for (int r = 0; r < 4; r++) acc[mf][nf][r] = 0.f;

    auto issue = [&](int it) {
        const uint32_t st = sbase + (it & 3) * STAGE_B;
        const int koff = it * 32;
        // Ah, Al: 64-row tiles (1 cpa each)
        cpa16(st + 0 * TILE_A + soffA, gA[0] + koff);
        cpa16(st + 1 * TILE_A + soffA, gA[1] + koff);
        // Bh, Bl: 128-row tiles (2 cpa each)
        const uint32_t bbase = st + 2 * TILE_A;
        cpa16(bbase + soffB0,           gB[0] + koff);
        cpa16(bbase + soffB1,           gB[0] + koff + bstride64);
        cpa16(bbase + TILE_BB + soffB0, gB[1] + koff);
        cpa16(bbase + TILE_BB + soffB1, gB[1] + koff + bstride64);
        CPA_COMMIT();
    };

    issue(0); issue(1); issue(2);

    for (int it = 0; it < NIT; it++) {
        const int rem = NIT - 1 - it;
        if (rem >= 2) CPA_WAIT(2);
        else if (rem == 1) CPA_WAIT(1);
        else CPA_WAIT(0);
        __syncthreads();
        if (it + 3 < NIT) issue(it + 3);

        const uint32_t stg = sbase + (it & 3) * STAGE_B;
        const uint32_t bstg = stg + 2 * TILE_A;
#pragma unroll
        for (int j = 0; j < 2; j++) {
            uint32_t ah[2][4], al[2][4], bh[2][4], bl[2][4];
#pragma unroll
            for (int mf = 0; mf < 2; mf++) {
                LDSM_X4(ah[mf][0], ah[mf][1], ah[mf][2], ah[mf][3],
                        stg + 0 * TILE_A + offA[mf][j]);
                LDSM_X4(al[mf][0], al[mf][1], al[mf][2], al[mf][3],
                        stg + 1 * TILE_A + offA[mf][j]);
            }
#pragma unroll
            for (int ng = 0; ng < 2; ng++) {
                LDSM_X4(bh[ng][0], bh[ng][1], bh[ng][2], bh[ng][3],
                        bstg + offB[ng][j]);
                LDSM_X4(bl[ng][0], bl[ng][1], bl[ng][2], bl[ng][3],
                        bstg + TILE_BB + offB[ng][j]);
            }
#pragma unroll
            for (int mf = 0; mf < 2; mf++) {
#pragma unroll
                for (int nf = 0; nf < 4; nf++) {
                    const int ng = nf >> 1, hb = (nf & 1) * 2;
                    MMA_BF16(acc[mf][nf], ah[mf], bh[ng][hb], bh[ng][hb + 1]);
                    MMA_BF16(acc[mf][nf], ah[mf], bl[ng][hb], bl[ng][hb + 1]);
                    MMA_BF16(acc[mf][nf], al[mf], bh[ng][hb], bh[ng][hb + 1]);
                }
            }
        }
    }

    // Epilogue (+bias)
    const int mbase = bm * 64 + warp_m * 32 + (lane >> 2);
    const int nbase = bn * 128 + warp_n * 32 + 2 * (lane & 3);
#pragma unroll
    for (int mf = 0; mf < 2; mf++) {
#pragma unroll
        for (int nf = 0; nf < 4; nf++) {
            const int m = mbase + mf * 16;
            const int n = nbase + nf * 8;
            const float bz0 = g_bias[n], bz1 = g_bias[n + 1];
            *(float2*)(out + (size_t)m * DOUT + n) =
                make_float2(acc[mf][nf][0] + bz0, acc[mf][nf][1] + bz1);
            *(float2*)(out + (size_t)(m + 8) * DOUT + n) =
                make_float2(acc[mf][nf][2] + bz0, acc[mf][nf][3] + bz1);
        }
    }
}

// ---------------------------------------------------------------------------
// Launch
// ---------------------------------------------------------------------------
extern "C" void kernel_launch(void* const* d_in, const int* in_sizes, int n_in,
                              void* d_out, int out_size) {
    const float* x     = (const float*)d_in[0];
    const float* Wemb  = (const float*)d_in[1];
    const float* bemb  = (const float*)d_in[2];
    const float* gamma = (const float*)d_in[3];
    const float* beta  = (const float*)d_in[4];
    const float* Wfc2  = (const float*)d_in[5];
    float* out = (float*)d_out;

    static int smem_set = 0;
    if (!smem_set) {
        cudaFuncSetAttribute(k_mma, cudaFuncAttributeMaxDynamicSharedMemorySize, SMEM_B);
        smem_set = 1;
    }

    k_embed<<<1184, 256>>>(x, Wemb, bemb);
    k_stats<<<96, 256>>>(gamma, beta);
    k_convB<<<512, 256>>>(Wfc2);
    k_mma<<<dim3(32, 8), 256, SMEM_B>>>(out);
}